// round 10
// baseline (speedup 1.0000x reference)
#include <cuda_runtime.h>
#include <cuda_bf16.h>
#include <cstdint>

// 4 lanes per (i,j) pair, 2 pairs per thread.
// Warp W of row i covers pairs [16W, 16W+16): lane l -> j = 16W + (l>>2),
// chunk = l&3, second pair j+8. Both warp-wide float4 stores are contiguous
// 512B blocks (1KB/warp total, 128B-aligned, minimal L1 wavefronts).
// R8 experiment: __stwt (write-through, no L2 allocate) on the write-once
// 285MB output stream, to test whether L2 write-allocate throttles DRAM.
// Output layout (reference order): [mask (N*N), rbf (N*N*16)], fp32.
__global__ __launch_bounds__(256)
void msb_edge_kernel(const float* __restrict__ pos,
                     const int* __restrict__ batch,   // int32
                     const float* __restrict__ centers,
                     const float* __restrict__ width,
                     float* __restrict__ out_mask,
                     float* __restrict__ out_rbf,
                     int n)
{
    const unsigned tid = blockIdx.x * blockDim.x + threadIdx.x; // n*2 lanes/row
    const unsigned W = tid >> 5;          // warp index within row
    const unsigned l = tid & 31;
    const int   j0    = (int)((W << 4) + (l >> 2));  // first pair
    const int   j1    = j0 + 8;                      // second pair
    const int   chunk = (int)(l & 3);
    if (j1 >= n && j0 >= n) return;

    const int i = blockIdx.y;
    const int bi = batch[i];              // broadcast (L1-resident)
    const float w = *width;               // broadcast
    const int c0 = chunk * 4;
    const float cA = __ldg(&centers[c0 + 0]);
    const float cB = __ldg(&centers[c0 + 1]);
    const float cC = __ldg(&centers[c0 + 2]);
    const float cD = __ldg(&centers[c0 + 3]);

    const float px = pos[3 * i + 0];
    const float py = pos[3 * i + 1];
    const float pz = pos[3 * i + 2];

    float4* __restrict__ rbf4 = reinterpret_cast<float4*>(out_rbf);
    const unsigned rowbase = (unsigned)i * (unsigned)(4 * n);

    #pragma unroll
    for (int p = 0; p < 2; ++p) {
        const int j = (p == 0) ? j0 : j1;
        if (j >= n) break;

        float4 outv  = make_float4(0.f, 0.f, 0.f, 0.f);
        float  maskv = 0.0f;

        const int bj = batch[j];          // coalesced (8 consecutive ints/warp)
        if ((bi == bj) && (i != j)) {
            // reference: diff = pos[i]-pos[j] + 1e-10 per comp; dist = ||diff||
            float dx = px - pos[3 * j + 0] + 1e-10f;
            float dy = py - pos[3 * j + 1] + 1e-10f;
            float dz = pz - pos[3 * j + 2] + 1e-10f;
            float d2 = dx * dx + dy * dy + dz * dz;
            if (d2 < 64.0f) {             // dist < CUTOFF(=8); sqrt monotone
                const float d   = sqrtf(d2);
                const float inv = __fdividef(0.5f, w * w);
                float t0 = d - cA, t1 = d - cB, t2 = d - cC, t3 = d - cD;
                outv = make_float4(__expf(-t0 * t0 * inv),
                                   __expf(-t1 * t1 * inv),
                                   __expf(-t2 * t2 * inv),
                                   __expf(-t3 * t3 * inv));
                maskv = 1.0f;
            }
        }

        // rbf float4 index: i*4n + j*4 + chunk
        __stwt(rbf4 + (rowbase + (unsigned)j * 4u + (unsigned)chunk), outv);
        if (chunk == 0) {
            __stwt(out_mask + (unsigned)i * (unsigned)n + (unsigned)j, maskv);
        }
    }
}

extern "C" void kernel_launch(void* const* d_in, const int* in_sizes, int n_in,
                              void* d_out, int out_size)
{
    const float* pos     = (const float*)d_in[0];
    const int*   batch   = (const int*)d_in[1];
    const float* centers = (const float*)d_in[2];
    const float* width   = (const float*)d_in[3];

    const int n = in_sizes[0] / 3;          // pos is [N,3]
    const size_t nn = (size_t)n * (size_t)n;

    float* out      = (float*)d_out;
    float* out_mask = out;        // [N*N]
    float* out_rbf  = out + nn;   // [N*N*16]

    // n*2 lanes per row (each thread covers 2 pairs).
    dim3 block(256, 1, 1);
    dim3 grid((unsigned)((n * 2 + 255) / 256), (unsigned)n, 1);
    msb_edge_kernel<<<grid, block>>>(pos, batch, centers, width,
                                     out_mask, out_rbf, n);
}

// round 11
// speedup vs baseline: 1.0082x; 1.0082x over previous
#include <cuda_runtime.h>
#include <cuda_bf16.h>
#include <cstdint>

// 2 lanes per (i,j) pair, one 256-bit store per thread (Blackwell STG.256).
// Warp W of row i covers pairs [16W, 16W+16): lane l -> j = 16W + (l>>1),
// half = l&1 (which 8 of the 16 rbf values). A warp-wide st.global.v8.f32 is
// 1KB fully contiguous: half the store instructions / LSU issue cost / index
// math of the float4 version, identical byte stream (285MB, ~7.1TB/s
// steady-state = near HBM write ceiling).
// Output layout (reference order): [mask (N*N), rbf (N*N*16)], fp32.

__device__ __forceinline__ void stg256(float* p,
                                       float v0, float v1, float v2, float v3,
                                       float v4, float v5, float v6, float v7)
{
    asm volatile("st.global.cs.v8.f32 [%0], {%1,%2,%3,%4,%5,%6,%7,%8};"
                 :: "l"(p), "f"(v0), "f"(v1), "f"(v2), "f"(v3),
                    "f"(v4), "f"(v5), "f"(v6), "f"(v7)
                 : "memory");
}

__global__ __launch_bounds__(256)
void msb_edge_kernel(const float* __restrict__ pos,
                     const int* __restrict__ batch,   // int32
                     const float* __restrict__ centers,
                     const float* __restrict__ width,
                     float* __restrict__ out_mask,
                     float* __restrict__ out_rbf,
                     int n)
{
    const unsigned tid = blockIdx.x * blockDim.x + threadIdx.x; // n*2 lanes/row
    const unsigned W = tid >> 5;                 // warp index within row
    const unsigned l = tid & 31;
    const int j    = (int)((W << 4) + (l >> 1)); // pair column
    const int half = (int)(l & 1);               // which 8 rbf values
    if (j >= n) return;

    const int i = blockIdx.y;
    const int bi = batch[i];                     // broadcast (L1-resident)
    const int bj = batch[j];                     // coalesced

    float v0 = 0.f, v1 = 0.f, v2 = 0.f, v3 = 0.f;
    float v4 = 0.f, v5 = 0.f, v6 = 0.f, v7 = 0.f;
    float maskv = 0.0f;

    if ((bi == bj) && (i != j)) {
        // reference: diff = pos[i]-pos[j] + 1e-10 per comp; dist = ||diff||
        float dx = pos[3 * i + 0] - pos[3 * j + 0] + 1e-10f;
        float dy = pos[3 * i + 1] - pos[3 * j + 1] + 1e-10f;
        float dz = pos[3 * i + 2] - pos[3 * j + 2] + 1e-10f;
        float d2 = dx * dx + dy * dy + dz * dz;
        if (d2 < 64.0f) {                        // dist < CUTOFF(=8)
            const float d   = sqrtf(d2);
            const float w   = *width;            // broadcast, cached
            const float inv = __fdividef(0.5f, w * w);
            const int   c0  = half * 8;
            float t0 = d - __ldg(&centers[c0 + 0]);
            float t1 = d - __ldg(&centers[c0 + 1]);
            float t2 = d - __ldg(&centers[c0 + 2]);
            float t3 = d - __ldg(&centers[c0 + 3]);
            float t4 = d - __ldg(&centers[c0 + 4]);
            float t5 = d - __ldg(&centers[c0 + 5]);
            float t6 = d - __ldg(&centers[c0 + 6]);
            float t7 = d - __ldg(&centers[c0 + 7]);
            v0 = __expf(-t0 * t0 * inv);
            v1 = __expf(-t1 * t1 * inv);
            v2 = __expf(-t2 * t2 * inv);
            v3 = __expf(-t3 * t3 * inv);
            v4 = __expf(-t4 * t4 * inv);
            v5 = __expf(-t5 * t5 * inv);
            v6 = __expf(-t6 * t6 * inv);
            v7 = __expf(-t7 * t7 * inv);
            maskv = 1.0f;
        }
    }

    // rbf element offset: i*16n + j*16 + half*8   (32B-aligned for STG.256)
    float* dst = out_rbf + (size_t)((unsigned)i) * (unsigned)(16 * n)
                         + (unsigned)j * 16u + (unsigned)half * 8u;
    stg256(dst, v0, v1, v2, v3, v4, v5, v6, v7);

    if (half == 0) {
        __stcs(out_mask + (size_t)((unsigned)i) * (unsigned)n + (unsigned)j,
               maskv);
    }
}

extern "C" void kernel_launch(void* const* d_in, const int* in_sizes, int n_in,
                              void* d_out, int out_size)
{
    const float* pos     = (const float*)d_in[0];
    const int*   batch   = (const int*)d_in[1];
    const float* centers = (const float*)d_in[2];
    const float* width   = (const float*)d_in[3];

    const int n = in_sizes[0] / 3;          // pos is [N,3]
    const size_t nn = (size_t)n * (size_t)n;

    float* out      = (float*)d_out;
    float* out_mask = out;        // [N*N]
    float* out_rbf  = out + nn;   // [N*N*16]

    // 2 lanes per pair: n*2 lanes per row i.
    dim3 block(256, 1, 1);
    dim3 grid((unsigned)((n * 2 + 255) / 256), (unsigned)n, 1);
    msb_edge_kernel<<<grid, block>>>(pos, batch, centers, width,
                                     out_mask, out_rbf, n);
}